// round 6
// baseline (speedup 1.0000x reference)
#include <cuda_runtime.h>
#include <cuda_bf16.h>
#include <math.h>
#include <stdint.h>

#define Bb 2
#define Ll 2048
#define Dd 1024
#define Hh 16
#define NT (Bb*Ll)          // 4096 tokens
#define ATT_SCALE 0.125f    // 1/sqrt(64)

// ---------------------------------------------------------------------------
// Scratch (device globals — allocation-free per harness rules)
// ---------------------------------------------------------------------------
__device__ float g_qkv[(size_t)NT * 3 * Dd];   // [token][3*D]

__device__ __nv_bfloat16 g_xhi[(size_t)NT * Dd];
__device__ __nv_bfloat16 g_xlo[(size_t)NT * Dd];
__device__ __nv_bfloat16 g_aohi[(size_t)NT * Dd];   // attn out [token][h*64+d]
__device__ __nv_bfloat16 g_aolo[(size_t)NT * Dd];
__device__ __nv_bfloat16 g_wqTh[(size_t)3 * Dd * Dd];
__device__ __nv_bfloat16 g_wqTl[(size_t)3 * Dd * Dd];
__device__ __nv_bfloat16 g_woTh[(size_t)Dd * Dd];
__device__ __nv_bfloat16 g_woTl[(size_t)Dd * Dd];
// head-major [b][h][l][64] bf16 hi/lo
__device__ __nv_bfloat16 g_qhi[(size_t)NT * Dd];
__device__ __nv_bfloat16 g_qlo[(size_t)NT * Dd];
__device__ __nv_bfloat16 g_khi[(size_t)NT * Dd];
__device__ __nv_bfloat16 g_klo[(size_t)NT * Dd];
__device__ __nv_bfloat16 g_vhi[(size_t)NT * Dd];
__device__ __nv_bfloat16 g_vlo[(size_t)NT * Dd];

// ---------------------------------------------------------------------------
// helpers
// ---------------------------------------------------------------------------
__device__ __forceinline__ uint32_t smem_u32(const void* p) {
    uint32_t a;
    asm("{ .reg .u64 t; cvta.to.shared.u64 t, %1; cvt.u32.u64 %0, t; }"
        : "=r"(a) : "l"(p));
    return a;
}
__device__ __forceinline__ void ldsm4(uint32_t* r, uint32_t addr) {
    asm volatile("ldmatrix.sync.aligned.m8n8.x4.shared.b16 {%0,%1,%2,%3}, [%4];"
        : "=r"(r[0]), "=r"(r[1]), "=r"(r[2]), "=r"(r[3]) : "r"(addr));
}
__device__ __forceinline__ void ldsm4t(uint32_t* r, uint32_t addr) {
    asm volatile("ldmatrix.sync.aligned.m8n8.x4.trans.shared.b16 {%0,%1,%2,%3}, [%4];"
        : "=r"(r[0]), "=r"(r[1]), "=r"(r[2]), "=r"(r[3]) : "r"(addr));
}
__device__ __forceinline__ void mma16816(float* d, const uint32_t* a, const uint32_t* b) {
    asm volatile("mma.sync.aligned.m16n8k16.row.col.f32.bf16.bf16.f32 "
        "{%0,%1,%2,%3}, {%4,%5,%6,%7}, {%8,%9}, {%0,%1,%2,%3};"
        : "+f"(d[0]), "+f"(d[1]), "+f"(d[2]), "+f"(d[3])
        : "r"(a[0]), "r"(a[1]), "r"(a[2]), "r"(a[3]), "r"(b[0]), "r"(b[1]));
}
__device__ __forceinline__ void cp_async16(uint32_t sdst, const void* gsrc) {
    asm volatile("cp.async.cg.shared.global [%0], [%1], 16;" :: "r"(sdst), "l"(gsrc));
}
#define CP_COMMIT() asm volatile("cp.async.commit_group;" ::: "memory")
#define CP_WAIT0()  asm volatile("cp.async.wait_group 0;" ::: "memory")

__device__ __forceinline__ uint32_t packbf(float a, float b) {
    __nv_bfloat162 h = __floats2bfloat162_rn(a, b);
    return *(uint32_t*)&h;
}

// ---------------------------------------------------------------------------
// split fp32 -> bf16 hi/lo
// ---------------------------------------------------------------------------
__global__ void __launch_bounds__(256) split_hilo(const float* __restrict__ in,
                                                  __nv_bfloat16* __restrict__ hi,
                                                  __nv_bfloat16* __restrict__ lo)
{
    int i = blockIdx.x * 256 + threadIdx.x;
    float4 v = ((const float4*)in)[i];
    __nv_bfloat16 hx = __float2bfloat16_rn(v.x);
    __nv_bfloat16 hy = __float2bfloat16_rn(v.y);
    __nv_bfloat16 hz = __float2bfloat16_rn(v.z);
    __nv_bfloat16 hw = __float2bfloat16_rn(v.w);
    __nv_bfloat162* h2 = (__nv_bfloat162*)hi;
    __nv_bfloat162* l2 = (__nv_bfloat162*)lo;
    h2[2 * i]     = __nv_bfloat162(hx, hy);
    h2[2 * i + 1] = __nv_bfloat162(hz, hw);
    l2[2 * i]     = __nv_bfloat162(__float2bfloat16_rn(v.x - __bfloat162float(hx)),
                                   __float2bfloat16_rn(v.y - __bfloat162float(hy)));
    l2[2 * i + 1] = __nv_bfloat162(__float2bfloat16_rn(v.z - __bfloat162float(hz)),
                                   __float2bfloat16_rn(v.w - __bfloat162float(hw)));
}

// ---------------------------------------------------------------------------
// split + transpose: W[K][N] fp32 -> hiT/loT [N][K] bf16
// ---------------------------------------------------------------------------
__global__ void __launch_bounds__(256) splitT(const float* __restrict__ W,
                                              __nv_bfloat16* __restrict__ hiT,
                                              __nv_bfloat16* __restrict__ loT,
                                              int K, int N)
{
    __shared__ float t[32][33];
    int n0 = blockIdx.x * 32, k0 = blockIdx.y * 32;
    int tx = threadIdx.x, ty = threadIdx.y;
#pragma unroll
    for (int r = 0; r < 4; r++)
        t[ty + r * 8][tx] = W[(size_t)(k0 + ty + r * 8) * N + n0 + tx];
    __syncthreads();
#pragma unroll
    for (int r = 0; r < 4; r++) {
        int n = ty + r * 8;
        float v = t[tx][n];
        __nv_bfloat16 h = __float2bfloat16_rn(v);
        hiT[(size_t)(n0 + n) * K + k0 + tx] = h;
        loT[(size_t)(n0 + n) * K + k0 + tx] =
            __float2bfloat16_rn(v - __bfloat162float(h));
    }
}

// ---------------------------------------------------------------------------
// HMMA GEMM: 256x128 tile / CTA, 512 threads, 16 warps, K-chunk 32, 2 stages.
// Warp (wm = wid&3, wn = wid>>2) owns rows wm*64..+64, cols wn*32..+32.
// smem stage: Ahi[256x80] Alo[256x80] Bhi[128x80] Blo[128x80] = 61440 B.
// ---------------------------------------------------------------------------
#define ROWB 80u
#define A_TILEB (256u * ROWB)        // 20480
#define B_TILEB (128u * ROWB)        // 10240
#define STAGE2 (2u * A_TILEB + 2u * B_TILEB)   // 61440

__global__ void __launch_bounds__(512, 1) gemm_mma(const __nv_bfloat16* __restrict__ Ahi,
                                                   const __nv_bfloat16* __restrict__ Alo,
                                                   const __nv_bfloat16* __restrict__ Bhi,
                                                   const __nv_bfloat16* __restrict__ Blo,
                                                   float* __restrict__ C,
                                                   int M, int N, int K)
{
    extern __shared__ char gsm[];
    const uint32_t sb = smem_u32(gsm);

    const int tid = threadIdx.x;
    const int wid = tid >> 5, lane = tid & 31;
    const int tile_n = blockIdx.x * 128, tile_m = blockIdx.y * 256;
    const int wm = wid & 3, wn = wid >> 2;
    const int NC = K >> 5;

    auto prefetch = [&](int kc, int s) {
        const uint32_t st = sb + (uint32_t)s * STAGE2;
#pragma unroll
        for (int it = 0; it < 6; it++) {
            int idx = it * 512 + tid;        // 0..3071
            int r = idx >> 2;                // 0..767
            int q = idx & 3;                 // 16B quarter of a 64B row
            const __nv_bfloat16* src;
            int grow;
            uint32_t dst;
            if (r < 256)      { src = Ahi; grow = tile_m + r;         dst = (uint32_t)r * ROWB; }
            else if (r < 512) { src = Alo; grow = tile_m + (r - 256); dst = A_TILEB + (uint32_t)(r - 256) * ROWB; }
            else if (r < 640) { src = Bhi; grow = tile_n + (r - 512); dst = 2u * A_TILEB + (uint32_t)(r - 512) * ROWB; }
            else              { src = Blo; grow = tile_n + (r - 640); dst = 2u * A_TILEB + B_TILEB + (uint32_t)(r - 640) * ROWB; }
            cp_async16(st + dst + q * 16, src + (size_t)grow * K + kc * 32 + q * 8);
        }
        CP_COMMIT();
    };

    float acc[4][4][4];
#pragma unroll
    for (int mi = 0; mi < 4; mi++)
#pragma unroll
        for (int ni = 0; ni < 4; ni++)
#pragma unroll
            for (int e = 0; e < 4; e++) acc[mi][ni][e] = 0.f;

    prefetch(0, 0);

    const uint32_t a_row = (uint32_t)(lane & 15);
    const uint32_t a_kgrp = (uint32_t)(lane >> 4) * 16;
    const uint32_t b_n = (uint32_t)((lane & 7) + ((lane >> 4) << 3));
    const uint32_t b_kgrp = (uint32_t)((lane >> 3) & 1) * 16;

    for (int kc = 0; kc < NC; kc++) {
        const int s = kc & 1;
        CP_WAIT0();
        __syncthreads();
        if (kc + 1 < NC) prefetch(kc + 1, s ^ 1);

        const uint32_t sA  = sb + (uint32_t)s * STAGE2;
        const uint32_t sAl = sA + A_TILEB;
        const uint32_t sB  = sA + 2u * A_TILEB;
        const uint32_t sBl = sB + B_TILEB;

#pragma unroll
        for (int k16 = 0; k16 < 2; k16++) {
            const uint32_t kb = (uint32_t)k16 * 32;
            uint32_t ah[4][4], al[4][4], bh[4][2], bl[4][2];
#pragma unroll
            for (int mi = 0; mi < 4; mi++) {
                uint32_t off = (uint32_t)(wm * 64 + mi * 16 + a_row) * ROWB + kb + a_kgrp;
                ldsm4(ah[mi], sA + off);
                ldsm4(al[mi], sAl + off);
            }
#pragma unroll
            for (int nh = 0; nh < 2; nh++) {
                uint32_t off = (uint32_t)(wn * 32 + nh * 16 + b_n) * ROWB + kb + b_kgrp;
                uint32_t r[4];
                ldsm4(r, sB + off);
                bh[nh * 2][0] = r[0]; bh[nh * 2][1] = r[1];
                bh[nh * 2 + 1][0] = r[2]; bh[nh * 2 + 1][1] = r[3];
                ldsm4(r, sBl + off);
                bl[nh * 2][0] = r[0]; bl[nh * 2][1] = r[1];
                bl[nh * 2 + 1][0] = r[2]; bl[nh * 2 + 1][1] = r[3];
            }
#pragma unroll
            for (int mi = 0; mi < 4; mi++)
#pragma unroll
                for (int ni = 0; ni < 4; ni++)
                    mma16816(acc[mi][ni], ah[mi], bh[ni]);
#pragma unroll
            for (int mi = 0; mi < 4; mi++)
#pragma unroll
                for (int ni = 0; ni < 4; ni++)
                    mma16816(acc[mi][ni], ah[mi], bl[ni]);
#pragma unroll
            for (int mi = 0; mi < 4; mi++)
#pragma unroll
                for (int ni = 0; ni < 4; ni++)
                    mma16816(acc[mi][ni], al[mi], bh[ni]);
        }
    }

#pragma unroll
    for (int mi = 0; mi < 4; mi++) {
        const int r0 = tile_m + wm * 64 + mi * 16 + (lane >> 2);
#pragma unroll
        for (int ni = 0; ni < 4; ni++) {
            const int c = tile_n + wn * 32 + ni * 8 + 2 * (lane & 3);
            *(float2*)&C[(size_t)r0 * N + c] =
                make_float2(acc[mi][ni][0], acc[mi][ni][1]);
            *(float2*)&C[(size_t)(r0 + 8) * N + c] =
                make_float2(acc[mi][ni][2], acc[mi][ni][3]);
        }
    }
}

// ---------------------------------------------------------------------------
// RoPE: g_qkv fp32 -> head-major bf16 hi/lo q,k,v
// ---------------------------------------------------------------------------
__global__ void __launch_bounds__(256) rope_kernel(const float* __restrict__ cosb,
                                                   const float* __restrict__ sinb)
{
    int idx = blockIdx.x * blockDim.x + threadIdx.x;   // < NT*Hh*32
    int i = idx & 31;
    int h = (idx >> 5) & 15;
    int t = idx >> 9;
    int b = t >> 11;
    int l = t & (Ll - 1);

    float c = cosb[(size_t)t * (Dd / 2) + h * 32 + i];
    float s = sinb[(size_t)t * (Dd / 2) + h * 32 + i];

    const float* row = &g_qkv[(size_t)t * 3 * Dd];
    float q1 = row[h * 64 + i],            q2 = row[h * 64 + 32 + i];
    float k1 = row[Dd + h * 64 + i],       k2 = row[Dd + h * 64 + 32 + i];
    float v1 = row[2 * Dd + h * 64 + i],   v2 = row[2 * Dd + h * 64 + 32 + i];

    float qa = q1 * c - q2 * s, qb = q1 * s + q2 * c;
    float ka = k1 * c - k2 * s, kb = k1 * s + k2 * c;

    size_t o = ((size_t)(b * Hh + h) * Ll + l) * 64;
#define SPLIT_ST(arr_hi, arr_lo, off, val) do { \
        __nv_bfloat16 _h = __float2bfloat16_rn(val); \
        arr_hi[(o) + (off)] = _h; \
        arr_lo[(o) + (off)] = __float2bfloat16_rn((val) - __bfloat162float(_h)); \
    } while (0)
    SPLIT_ST(g_qhi, g_qlo, i,      qa);
    SPLIT_ST(g_qhi, g_qlo, 32 + i, qb);
    SPLIT_ST(g_khi, g_klo, i,      ka);
    SPLIT_ST(g_khi, g_klo, 32 + i, kb);
    SPLIT_ST(g_vhi, g_vlo, i,      v1);
    SPLIT_ST(g_vhi, g_vlo, 32 + i, v2);
#undef SPLIT_ST
}

// ---------------------------------------------------------------------------
// HMMA flash attention (R5 layout, + occupancy 2).
// ---------------------------------------------------------------------------
#define FROWB 144u
#define FMATB (64u * FROWB)     // 9216
#define FSTAGEB (4u * FMATB)    // 36864
#define FSMEM (2u * FSTAGEB)    // 73728

__global__ void __launch_bounds__(256, 2) flash_mma(const int* __restrict__ mask)
{
    extern __shared__ char fsm_[];
    const uint32_t sb = smem_u32(fsm_);
    __shared__ float mks[2][64];

    const int qt = blockIdx.x, h = blockIdx.y, b = blockIdx.z;
    const int tid = threadIdx.x;
    const int wid = tid >> 5, lane = tid & 31;

    const size_t hoff = (size_t)(b * Hh + h) * Ll * 64;
    const __nv_bfloat16* Khi = g_khi + hoff;
    const __nv_bfloat16* Klo = g_klo + hoff;
    const __nv_bfloat16* Vhi = g_vhi + hoff;
    const __nv_bfloat16* Vlo = g_vlo + hoff;

    // ---- prologue: stage Q (hi/lo) into stage-1 area, prefetch KV tile 0 ----
    {
        const __nv_bfloat16* Qs[2] = {g_qhi + hoff, g_qlo + hoff};
#pragma unroll
        for (int it = 0; it < 8; it++) {
            int idx = it * 256 + tid;           // 0..2047
            int mat = idx >> 10;                // 0..1
            int r = (idx >> 3) & 127;           // 0..127
            int q = idx & 7;                    // 0..7
            const void* gp = Qs[mat] + (size_t)(qt * 128 + r) * 64 + q * 8;
            uint32_t sp = sb + FSTAGEB + mat * (128u * FROWB) + r * FROWB + q * 16;
            cp_async16(sp, gp);
        }
        CP_COMMIT();
    }
    const __nv_bfloat16* kvsrc[4] = {Khi, Klo, Vhi, Vlo};
    auto prefetch = [&](int t, int s) {
#pragma unroll
        for (int it = 0; it < 8; it++) {
            int idx = it * 256 + tid;           // 0..2047
            int mat = idx >> 9;                 // 0..3
            int r = (idx >> 3) & 63;            // 0..63
            int q = idx & 7;                    // 0..7
            const void* gp = kvsrc[mat] + (size_t)(t * 64 + r) * 64 + q * 8;
            uint32_t sp = sb + (uint32_t)s * FSTAGEB + mat * FMATB + r * FROWB + q * 16;
            cp_async16(sp, gp);
        }
        CP_COMMIT();
        if (tid < 64)
            mks[s][tid] = mask[b * Ll + t * 64 + tid] ? 0.0f : -1e30f;
    };
    prefetch(0, 0);
    CP_WAIT0();
    __syncthreads();

    // ---- extract Q fragments ----
    uint32_t qhf[4][4], qlf[4][4];
    {
        const uint32_t qrow = (uint32_t)(lane & 15);
        const uint32_t qg = (uint32_t)(lane >> 4) * 16;
#pragma unroll
        for (int ki = 0; ki < 4; ki++) {
            uint32_t off = (uint32_t)(wid * 16 + qrow) * FROWB + ki * 32 + qg;
            ldsm4(qhf[ki], sb + FSTAGEB + off);
            ldsm4(qlf[ki], sb + FSTAGEB + 128u * FROWB + off);
        }
    }
    __syncthreads();

    float oacc[8][4];
#pragma unroll
    for (int ni = 0; ni < 8; ni++)
#pragma unroll
        for (int e = 0; e < 4; e++) oacc[ni][e] = 0.f;
    float m0 = -1e30f, m1 = -1e30f, l0 = 0.f, l1 = 0.f;

    const uint32_t krow = (uint32_t)((lane & 7) + ((lane >> 4) << 3));
    const uint32_t kg = (uint32_t)((lane >> 3) & 1) * 16;
    const uint32_t vrow = (uint32_t)(lane & 15);
    const uint32_t vg = (uint32_t)(lane >> 4) * 16;

    for (int t = 0; t < Ll / 64; t++) {
        const int s = t & 1;
        CP_WAIT0();
        __syncthreads();
        if (t + 1 < Ll / 64) prefetch(t + 1, s ^ 1);

        const uint32_t stK  = sb + (uint32_t)s * FSTAGEB;
        const uint32_t stKl = stK + FMATB;
        const uint32_t stV  = stK + 2 * FMATB;
        const uint32_t stVl = stK + 3 * FMATB;

        // ---- S = Q K^T ----
        float sacc[8][4];
#pragma unroll
        for (int ni = 0; ni < 8; ni++)
#pragma unroll
            for (int e = 0; e < 4; e++) sacc[ni][e] = 0.f;

#pragma unroll
        for (int nh = 0; nh < 4; nh++) {
#pragma unroll
            for (int ki = 0; ki < 4; ki++) {
                uint32_t off = (uint32_t)(nh * 16 + krow) * FROWB + ki * 32 + kg;
                uint32_t r[4], bh0[2], bh1[2], bl0[2], bl1[2];
                ldsm4(r, stK + off);
                bh0[0] = r[0]; bh0[1] = r[1]; bh1[0] = r[2]; bh1[1] = r[3];
                ldsm4(r, stKl + off);
                bl0[0] = r[0]; bl0[1] = r[1]; bl1[0] = r[2]; bl1[1] = r[3];
                mma16816(sacc[2 * nh],     qhf[ki], bh0);
                mma16816(sacc[2 * nh + 1], qhf[ki], bh1);
                mma16816(sacc[2 * nh],     qhf[ki], bl0);
                mma16816(sacc[2 * nh + 1], qhf[ki], bl1);
                mma16816(sacc[2 * nh],     qlf[ki], bh0);
                mma16816(sacc[2 * nh + 1], qlf[ki], bh1);
            }
        }

        // ---- online softmax ----
        float rmax0 = -1e30f, rmax1 = -1e30f;
        const int cq = 2 * (lane & 3);
#pragma unroll
        for (int ni = 0; ni < 8; ni++) {
            float mk0 = mks[s][ni * 8 + cq];
            float mk1 = mks[s][ni * 8 + cq + 1];
            sacc[ni][0] = sacc[ni][0] * ATT_SCALE + mk0;
            sacc[ni][1] = sacc[ni][1] * ATT_SCALE + mk1;
            sacc[ni][2] = sacc[ni][2] * ATT_SCALE + mk0;
            sacc[ni][3] = sacc[ni][3] * ATT_SCALE + mk1;
            rmax0 = fmaxf(rmax0, fmaxf(sacc[ni][0], sacc[ni][1]));
            rmax1 = fmaxf(rmax1, fmaxf(sacc[ni][2], sacc[ni][3]));
        }
        rmax0 = fmaxf(rmax0, __shfl_xor_sync(0xffffffffu, rmax0, 1));
        rmax0 = fmaxf(rmax0, __shfl_xor_sync(0xffffffffu, rmax0, 2));
        rmax1 = fmaxf(rmax1, __shfl_xor_sync(0xffffffffu, rmax1, 1));
        rmax1 = fmaxf(rmax1, __shfl_xor_sync(0xffffffffu, rmax1, 2));

        float mn0 = fmaxf(m0, rmax0), mn1 = fmaxf(m1, rmax1);
        float a0 = __expf(m0 - mn0), a1 = __expf(m1 - mn1);
        m0 = mn0; m1 = mn1;

        float rs0 = 0.f, rs1 = 0.f;
#pragma unroll
        for (int ni = 0; ni < 8; ni++) {
            sacc[ni][0] = __expf(sacc[ni][0] - mn0);
            sacc[ni][1] = __expf(sacc[ni][1] - mn0);
            sacc[ni][2] = __expf(sacc[ni][2] - mn1);
            sacc[ni][3] = __expf(sacc[ni][3] - mn1);
            rs0 += sacc[ni][0] + sacc[ni][1];
            rs1 += sacc[ni][2] + sacc[ni][3];
        }
        rs0 += __shfl_xor_sync(0xffffffffu, rs0, 1);
        rs0 += __shfl_xor_sync(0xffffffffu, rs0, 2);
        rs1 += __shfl_xor_sync(0xffffffffu, rs1, 1);
        rs1 += __shfl_xor_sync(0xffffffffu, rs1, 2);
        l0 = l0 * a0 + rs0;
        l1 = l1 * a1 + rs1;
#pragma unroll
        for (int ni = 0; ni < 8; ni++) {
            oacc[ni][0] *= a0; oacc[ni][1] *= a0;
            oacc[ni][2] *= a1; oacc[ni][3] *= a1;
        }

        // ---- O += P V ----
#pragma unroll
        for (int ki = 0; ki < 4; ki++) {
            uint32_t ph[4], pl[4];
            float* p0 = sacc[2 * ki];
            float* p1 = sacc[2 * ki + 1];
            ph[0] = packbf(p0[0], p0[1]);
            ph[1] = packbf(p0[2], p0[3]);
            ph[2] = packbf(p1[0], p1[1]);
            ph[3] = packbf(p1[2], p1[3]);
#pragma unroll
            for (int e = 0; e < 4; e++) {
                float* pp = (e < 2) ? p0 : p1;
                int b0 = (e & 1) * 2;
                float lo0 = pp[b0]     - __bfloat162float(__float2bfloat16_rn(pp[b0]));
                float lo1 = pp[b0 + 1] - __bfloat162float(__float2bfloat16_rn(pp[b0 + 1]));
                pl[e] = packbf(lo0, lo1);
            }
#pragma unroll
            for (int nh = 0; nh < 4; nh++) {
                uint32_t off = (uint32_t)(ki * 16 + vrow) * FROWB + nh * 32 + vg;
                uint32_t r[4], vh0[2], vh1[2], vl0[2], vl1[2];
                ldsm4t(r, stV + off);
                vh0[0] = r[0]; vh0[1] = r[1]; vh1[0] = r[2]; vh1[1] = r[3];
                ldsm4t(r, stVl + off);
                vl0[0] = r[0]; vl0[1] = r[1]; vl1[0] = r[2]; vl1[1] = r[3];
                mma16816(oacc[2 * nh],     ph, vh0);
                mma16816(oacc[2 * nh + 1], ph, vh1);
                mma16816(oacc[2 * nh],     ph, vl0);
                mma16816(oacc[2 * nh + 1], ph, vl1);
                mma16816(oacc[2 * nh],     pl, vh0);
                mma16816(oacc[2 * nh + 1], pl, vh1);
            }
        }
    }

    // ---- epilogue ----
    float inv0 = 1.0f / l0, inv1 = 1.0f / l1;
    const int tok0 = b * Ll + qt * 128 + wid * 16 + (lane >> 2);
    const int cbase = h * 64 + 2 * (lane & 3);
#pragma unroll
    for (int ni = 0; ni < 8; ni++) {
        float v00 = oacc[ni][0] * inv0, v01 = oacc[ni][1] * inv0;
        float v10 = oacc[ni][2] * inv1, v11 = oacc[ni][3] * inv1;
        size_t o0 = (size_t)tok0 * Dd + cbase + ni * 8;
        size_t o1 = (size_t)(tok0 + 8) * Dd + cbase + ni * 8;
        uint32_t h00 = packbf(v00, v01), h10 = packbf(v10, v11);
        *(uint32_t*)&g_aohi[o0] = h00;
        *(uint32_t*)&g_aohi[o1] = h10;
        __nv_bfloat162 hh0 = *(__nv_bfloat162*)&h00;
        __nv_bfloat162 hh1 = *(__nv_bfloat162*)&h10;
        *(uint32_t*)&g_aolo[o0] = packbf(v00 - __bfloat162float(hh0.x),
                                         v01 - __bfloat162float(hh0.y));
        *(uint32_t*)&g_aolo[o1] = packbf(v10 - __bfloat162float(hh1.x),
                                         v11 - __bfloat162float(hh1.y));
    }
}

// ---------------------------------------------------------------------------
extern "C" void kernel_launch(void* const* d_in, const int* in_sizes, int n_in,
                              void* d_out, int out_size)
{
    const float* x    = (const float*)d_in[0];
    const float* rc   = (const float*)d_in[1];
    const float* rs   = (const float*)d_in[2];
    const float* wqkv = (const float*)d_in[3];
    const float* wo   = (const float*)d_in[4];
    const int*   mask = (const int*)d_in[5];
    float* out = (float*)d_out;

    float *qkv_p;
    __nv_bfloat16 *xhi, *xlo, *aohi, *aolo, *wqTh, *wqTl, *woTh, *woTl;
    cudaGetSymbolAddress((void**)&qkv_p, g_qkv);
    cudaGetSymbolAddress((void**)&xhi, g_xhi);
    cudaGetSymbolAddress((void**)&xlo, g_xlo);
    cudaGetSymbolAddress((void**)&aohi, g_aohi);
    cudaGetSymbolAddress((void**)&aolo, g_aolo);
    cudaGetSymbolAddress((void**)&wqTh, g_wqTh);
    cudaGetSymbolAddress((void**)&wqTl, g_wqTl);
    cudaGetSymbolAddress((void**)&woTh, g_woTh);
    cudaGetSymbolAddress((void**)&woTl, g_woTl);

    const int GSM = 2 * (int)STAGE2;    // 122880
    cudaFuncSetAttribute((const void*)gemm_mma,
                         cudaFuncAttributeMaxDynamicSharedMemorySize, GSM);
    cudaFuncSetAttribute((const void*)flash_mma,
                         cudaFuncAttributeMaxDynamicSharedMemorySize, (int)FSMEM);

    // 0) splits
    split_hilo<<<(NT * Dd / 4) / 256, 256>>>(x, xhi, xlo);
    splitT<<<dim3(3 * Dd / 32, Dd / 32), dim3(32, 8)>>>(wqkv, wqTh, wqTl, Dd, 3 * Dd);
    splitT<<<dim3(Dd / 32, Dd / 32), dim3(32, 8)>>>(wo, woTh, woTl, Dd, Dd);

    // 1) QKV projection (HMMA, 256x128 tiles)
    gemm_mma<<<dim3(3 * Dd / 128, NT / 256), 512, GSM>>>(xhi, xlo, wqTh, wqTl,
                                                         qkv_p, NT, 3 * Dd, Dd);

    // 2) RoPE -> head-major bf16 hi/lo
    rope_kernel<<<(NT * Hh * 32) / 256, 256>>>(rc, rs);

    // 3) Flash attention (HMMA, 2 CTAs/SM)
    flash_mma<<<dim3(Ll / 128, Hh, Bb), 256, FSMEM>>>(mask);

    // 4) Output projection (HMMA)
    gemm_mma<<<dim3(Dd / 128, NT / 256), 512, GSM>>>(aohi, aolo, woTh, woTl,
                                                     out, NT, Dd, Dd);
}

// round 7
// speedup vs baseline: 1.3869x; 1.3869x over previous
#include <cuda_runtime.h>
#include <cuda_fp16.h>
#include <math.h>
#include <stdint.h>

#define Bb 2
#define Ll 2048
#define Dd 1024
#define Hh 16
#define NT (Bb*Ll)          // 4096 tokens
#define ATT_SCALE 0.125f    // 1/sqrt(64)

// ---------------------------------------------------------------------------
// Scratch (device globals — allocation-free per harness rules)
// ---------------------------------------------------------------------------
__device__ float g_qkv[(size_t)NT * 3 * Dd];   // [token][3*D]

__device__ __half g_xhi[(size_t)NT * Dd];
__device__ __half g_xlo[(size_t)NT * Dd];
__device__ __half g_aohi[(size_t)NT * Dd];     // attn out [token][h*64+d]
__device__ __half g_aolo[(size_t)NT * Dd];
__device__ __half g_wqTh[(size_t)3 * Dd * Dd]; // W_qkv^T [3072][1024] hi only
__device__ __half g_woTh[(size_t)Dd * Dd];     // W_o^T hi only
// head-major [b][h][l][64] fp16
__device__ __half g_qhi[(size_t)NT * Dd];
__device__ __half g_qlo[(size_t)NT * Dd];
__device__ __half g_khi[(size_t)NT * Dd];
__device__ __half g_vhi[(size_t)NT * Dd];

// ---------------------------------------------------------------------------
// helpers
// ---------------------------------------------------------------------------
__device__ __forceinline__ uint32_t smem_u32(const void* p) {
    uint32_t a;
    asm("{ .reg .u64 t; cvta.to.shared.u64 t, %1; cvt.u32.u64 %0, t; }"
        : "=r"(a) : "l"(p));
    return a;
}
__device__ __forceinline__ void ldsm4(uint32_t* r, uint32_t addr) {
    asm volatile("ldmatrix.sync.aligned.m8n8.x4.shared.b16 {%0,%1,%2,%3}, [%4];"
        : "=r"(r[0]), "=r"(r[1]), "=r"(r[2]), "=r"(r[3]) : "r"(addr));
}
__device__ __forceinline__ void ldsm4t(uint32_t* r, uint32_t addr) {
    asm volatile("ldmatrix.sync.aligned.m8n8.x4.trans.shared.b16 {%0,%1,%2,%3}, [%4];"
        : "=r"(r[0]), "=r"(r[1]), "=r"(r[2]), "=r"(r[3]) : "r"(addr));
}
__device__ __forceinline__ void mma16816(float* d, const uint32_t* a, const uint32_t* b) {
    asm volatile("mma.sync.aligned.m16n8k16.row.col.f32.f16.f16.f32 "
        "{%0,%1,%2,%3}, {%4,%5,%6,%7}, {%8,%9}, {%0,%1,%2,%3};"
        : "+f"(d[0]), "+f"(d[1]), "+f"(d[2]), "+f"(d[3])
        : "r"(a[0]), "r"(a[1]), "r"(a[2]), "r"(a[3]), "r"(b[0]), "r"(b[1]));
}
__device__ __forceinline__ void cp_async16(uint32_t sdst, const void* gsrc) {
    asm volatile("cp.async.cg.shared.global [%0], [%1], 16;" :: "r"(sdst), "l"(gsrc));
}
#define CP_COMMIT() asm volatile("cp.async.commit_group;" ::: "memory")
#define CP_WAIT0()  asm volatile("cp.async.wait_group 0;" ::: "memory")

__device__ __forceinline__ uint32_t packh(float a, float b) {
    __half2 h = __floats2half2_rn(a, b);
    return *(uint32_t*)&h;
}

// ---------------------------------------------------------------------------
// split fp32 -> fp16 hi/lo
// ---------------------------------------------------------------------------
__global__ void __launch_bounds__(256) split_hilo(const float* __restrict__ in,
                                                  __half* __restrict__ hi,
                                                  __half* __restrict__ lo)
{
    int i = blockIdx.x * 256 + threadIdx.x;
    float4 v = ((const float4*)in)[i];
    __half hx = __float2half_rn(v.x);
    __half hy = __float2half_rn(v.y);
    __half hz = __float2half_rn(v.z);
    __half hw = __float2half_rn(v.w);
    __half2* h2 = (__half2*)hi;
    __half2* l2 = (__half2*)lo;
    h2[2 * i]     = __half2(hx, hy);
    h2[2 * i + 1] = __half2(hz, hw);
    l2[2 * i]     = __half2(__float2half_rn(v.x - __half2float(hx)),
                            __float2half_rn(v.y - __half2float(hy)));
    l2[2 * i + 1] = __half2(__float2half_rn(v.z - __half2float(hz)),
                            __float2half_rn(v.w - __half2float(hw)));
}

// ---------------------------------------------------------------------------
// transpose + fp16: W[K][N] fp32 -> hiT [N][K] fp16
// ---------------------------------------------------------------------------
__global__ void __launch_bounds__(256) splitT(const float* __restrict__ W,
                                              __half* __restrict__ hiT,
                                              int K, int N)
{
    __shared__ float t[32][33];
    int n0 = blockIdx.x * 32, k0 = blockIdx.y * 32;
    int tx = threadIdx.x, ty = threadIdx.y;
#pragma unroll
    for (int r = 0; r < 4; r++)
        t[ty + r * 8][tx] = W[(size_t)(k0 + ty + r * 8) * N + n0 + tx];
    __syncthreads();
#pragma unroll
    for (int r = 0; r < 4; r++) {
        int n = ty + r * 8;
        hiT[(size_t)(n0 + n) * K + k0 + tx] = __float2half_rn(t[tx][n]);
    }
}

// ---------------------------------------------------------------------------
// HMMA GEMM (fp16 2-term): C = (Ahi+Alo)[M,K] @ Bhi[N,K]^T
// 128x128 tile, 256 threads, K-chunk 32, 2 stages, 2 CTAs/SM.
// ---------------------------------------------------------------------------
#define ROWB 80u
#define TILEB (128u * ROWB)          // 10240
#define STAGE3 (3u * TILEB)          // 30720

__global__ void __launch_bounds__(256, 2) gemm_mma(const __half* __restrict__ Ahi,
                                                   const __half* __restrict__ Alo,
                                                   const __half* __restrict__ Bhi,
                                                   float* __restrict__ C,
                                                   int M, int N, int K)
{
    extern __shared__ char gsm[];
    const uint32_t sb = smem_u32(gsm);

    const int tid = threadIdx.x;
    const int wid = tid >> 5, lane = tid & 31;
    const int tile_n = blockIdx.x * 128, tile_m = blockIdx.y * 128;
    const int wm = wid & 1, wn = wid >> 1;
    const int NC = K >> 5;

    const __half* srcs[3] = {Ahi, Alo, Bhi};
    const int rb[3] = {tile_m, tile_m, tile_n};

    auto prefetch = [&](int kc, int s) {
        const uint32_t st = sb + (uint32_t)s * STAGE3;
#pragma unroll
        for (int it = 0; it < 6; it++) {
            int idx = it * 256 + tid;        // 0..1535
            int mat = idx >> 9;              // 0..2
            int r = (idx >> 2) & 127;        // 0..127
            int q = idx & 3;                 // 16B quarter of 64B row
            const void* gp = srcs[mat] + (size_t)(rb[mat] + r) * K + kc * 32 + q * 8;
            cp_async16(st + (uint32_t)mat * TILEB + (uint32_t)r * ROWB + q * 16, gp);
        }
        CP_COMMIT();
    };

    float acc[4][4][4];
#pragma unroll
    for (int mi = 0; mi < 4; mi++)
#pragma unroll
        for (int ni = 0; ni < 4; ni++)
#pragma unroll
            for (int e = 0; e < 4; e++) acc[mi][ni][e] = 0.f;

    prefetch(0, 0);

    const uint32_t a_row = (uint32_t)(lane & 15);
    const uint32_t a_kgrp = (uint32_t)(lane >> 4) * 16;
    const uint32_t b_n = (uint32_t)((lane & 7) + ((lane >> 4) << 3));
    const uint32_t b_kgrp = (uint32_t)((lane >> 3) & 1) * 16;

    for (int kc = 0; kc < NC; kc++) {
        const int s = kc & 1;
        CP_WAIT0();
        __syncthreads();
        if (kc + 1 < NC) prefetch(kc + 1, s ^ 1);

        const uint32_t sA  = sb + (uint32_t)s * STAGE3;
        const uint32_t sAl = sA + TILEB;
        const uint32_t sB  = sA + 2u * TILEB;

#pragma unroll
        for (int k16 = 0; k16 < 2; k16++) {
            const uint32_t kb = (uint32_t)k16 * 32;
            uint32_t ah[4][4], al[4][4], bh[4][2];
#pragma unroll
            for (int mi = 0; mi < 4; mi++) {
                uint32_t off = (uint32_t)(wm * 64 + mi * 16 + a_row) * ROWB + kb + a_kgrp;
                ldsm4(ah[mi], sA + off);
                ldsm4(al[mi], sAl + off);
            }
#pragma unroll
            for (int nh = 0; nh < 2; nh++) {
                uint32_t off = (uint32_t)(wn * 32 + nh * 16 + b_n) * ROWB + kb + b_kgrp;
                uint32_t r[4];
                ldsm4(r, sB + off);
                bh[nh * 2][0] = r[0]; bh[nh * 2][1] = r[1];
                bh[nh * 2 + 1][0] = r[2]; bh[nh * 2 + 1][1] = r[3];
            }
#pragma unroll
            for (int mi = 0; mi < 4; mi++)
#pragma unroll
                for (int ni = 0; ni < 4; ni++)
                    mma16816(acc[mi][ni], ah[mi], bh[ni]);
#pragma unroll
            for (int mi = 0; mi < 4; mi++)
#pragma unroll
                for (int ni = 0; ni < 4; ni++)
                    mma16816(acc[mi][ni], al[mi], bh[ni]);
        }
    }

#pragma unroll
    for (int mi = 0; mi < 4; mi++) {
        const int r0 = tile_m + wm * 64 + mi * 16 + (lane >> 2);
#pragma unroll
        for (int ni = 0; ni < 4; ni++) {
            const int c = tile_n + wn * 32 + ni * 8 + 2 * (lane & 3);
            *(float2*)&C[(size_t)r0 * N + c] =
                make_float2(acc[mi][ni][0], acc[mi][ni][1]);
            *(float2*)&C[(size_t)(r0 + 8) * N + c] =
                make_float2(acc[mi][ni][2], acc[mi][ni][3]);
        }
    }
}

// ---------------------------------------------------------------------------
// RoPE: g_qkv fp32 -> head-major fp16 (q: hi+lo, k/v: hi only)
// ---------------------------------------------------------------------------
__global__ void __launch_bounds__(256) rope_kernel(const float* __restrict__ cosb,
                                                   const float* __restrict__ sinb)
{
    int idx = blockIdx.x * blockDim.x + threadIdx.x;   // < NT*Hh*32
    int i = idx & 31;
    int h = (idx >> 5) & 15;
    int t = idx >> 9;
    int b = t >> 11;
    int l = t & (Ll - 1);

    float c = cosb[(size_t)t * (Dd / 2) + h * 32 + i];
    float s = sinb[(size_t)t * (Dd / 2) + h * 32 + i];

    const float* row = &g_qkv[(size_t)t * 3 * Dd];
    float q1 = row[h * 64 + i],            q2 = row[h * 64 + 32 + i];
    float k1 = row[Dd + h * 64 + i],       k2 = row[Dd + h * 64 + 32 + i];
    float v1 = row[2 * Dd + h * 64 + i],   v2 = row[2 * Dd + h * 64 + 32 + i];

    float qa = q1 * c - q2 * s, qb = q1 * s + q2 * c;
    float ka = k1 * c - k2 * s, kb = k1 * s + k2 * c;

    size_t o = ((size_t)(b * Hh + h) * Ll + l) * 64;
    {
        __half hq = __float2half_rn(qa);
        g_qhi[o + i] = hq;
        g_qlo[o + i] = __float2half_rn(qa - __half2float(hq));
        hq = __float2half_rn(qb);
        g_qhi[o + 32 + i] = hq;
        g_qlo[o + 32 + i] = __float2half_rn(qb - __half2float(hq));
    }
    g_khi[o + i]      = __float2half_rn(ka);
    g_khi[o + 32 + i] = __float2half_rn(kb);
    g_vhi[o + i]      = __float2half_rn(v1);
    g_vhi[o + 32 + i] = __float2half_rn(v2);
}

// ---------------------------------------------------------------------------
// HMMA flash attention (fp16 2-term).
// CTA: 128 q-rows of one (b,h). 8 warps. KV tile 64, double buffered.
// smem: stage s in {0,1}: Khi[64x144] Vhi[64x144]; Q(hi,lo)[128x144] once.
// ---------------------------------------------------------------------------
#define FROWB 144u
#define FMATB (64u * FROWB)     // 9216
#define FSTG (2u * FMATB)       // 18432 per stage
#define FQOFF (2u * FSTG)       // 36864
#define FSMEM (FQOFF + 2u * 128u * FROWB)   // 73728

__global__ void __launch_bounds__(256, 2) flash_mma(const int* __restrict__ mask)
{
    extern __shared__ char fsm_[];
    const uint32_t sb = smem_u32(fsm_);
    __shared__ float mks[2][64];

    const int qt = blockIdx.x, h = blockIdx.y, b = blockIdx.z;
    const int tid = threadIdx.x;
    const int wid = tid >> 5, lane = tid & 31;

    const size_t hoff = (size_t)(b * Hh + h) * Ll * 64;
    const __half* Khi = g_khi + hoff;
    const __half* Vhi = g_vhi + hoff;

    // ---- prologue: stage Q (hi/lo), prefetch KV tile 0 ----
    {
        const __half* Qs[2] = {g_qhi + hoff, g_qlo + hoff};
#pragma unroll
        for (int it = 0; it < 8; it++) {
            int idx = it * 256 + tid;           // 0..2047
            int mat = idx >> 10;                // 0..1
            int r = (idx >> 3) & 127;           // 0..127
            int q = idx & 7;                    // 0..7
            const void* gp = Qs[mat] + (size_t)(qt * 128 + r) * 64 + q * 8;
            uint32_t sp = sb + FQOFF + mat * (128u * FROWB) + r * FROWB + q * 16;
            cp_async16(sp, gp);
        }
        CP_COMMIT();
    }
    // KV: 2 mats x 64 rows x 8 quarters = 1024 chunks -> 4 iters
    auto prefetch = [&](int t, int s) {
#pragma unroll
        for (int it = 0; it < 4; it++) {
            int idx = it * 256 + tid;           // 0..1023
            int mat = idx >> 9;                 // 0..1 (K,V)
            int r = (idx >> 3) & 63;            // 0..63
            int q = idx & 7;                    // 0..7
            const __half* src = mat ? Vhi : Khi;
            const void* gp = src + (size_t)(t * 64 + r) * 64 + q * 8;
            uint32_t sp = sb + (uint32_t)s * FSTG + mat * FMATB + r * FROWB + q * 16;
            cp_async16(sp, gp);
        }
        CP_COMMIT();
        if (tid < 64)
            mks[s][tid] = mask[b * Ll + t * 64 + tid] ? 0.0f : -1e30f;
    };
    prefetch(0, 0);
    CP_WAIT0();
    __syncthreads();

    // ---- extract Q fragments (register-resident) ----
    uint32_t qhf[4][4], qlf[4][4];
    {
        const uint32_t qrow = (uint32_t)(lane & 15);
        const uint32_t qg = (uint32_t)(lane >> 4) * 16;
#pragma unroll
        for (int ki = 0; ki < 4; ki++) {
            uint32_t off = (uint32_t)(wid * 16 + qrow) * FROWB + ki * 32 + qg;
            ldsm4(qhf[ki], sb + FQOFF + off);
            ldsm4(qlf[ki], sb + FQOFF + 128u * FROWB + off);
        }
    }

    float oacc[8][4];
#pragma unroll
    for (int ni = 0; ni < 8; ni++)
#pragma unroll
        for (int e = 0; e < 4; e++) oacc[ni][e] = 0.f;
    float m0 = -1e30f, m1 = -1e30f, l0 = 0.f, l1 = 0.f;

    const uint32_t krow = (uint32_t)((lane & 7) + ((lane >> 4) << 3));
    const uint32_t kg = (uint32_t)((lane >> 3) & 1) * 16;
    const uint32_t vrow = (uint32_t)(lane & 15);
    const uint32_t vg = (uint32_t)(lane >> 4) * 16;

    for (int t = 0; t < Ll / 64; t++) {
        const int s = t & 1;
        CP_WAIT0();
        __syncthreads();
        if (t + 1 < Ll / 64) prefetch(t + 1, s ^ 1);

        const uint32_t stK = sb + (uint32_t)s * FSTG;
        const uint32_t stV = stK + FMATB;

        // ---- S = Q K^T (2-term: qh*kh + ql*kh) ----
        float sacc[8][4];
#pragma unroll
        for (int ni = 0; ni < 8; ni++)
#pragma unroll
            for (int e = 0; e < 4; e++) sacc[ni][e] = 0.f;

#pragma unroll
        for (int nh = 0; nh < 4; nh++) {
#pragma unroll
            for (int ki = 0; ki < 4; ki++) {
                uint32_t off = (uint32_t)(nh * 16 + krow) * FROWB + ki * 32 + kg;
                uint32_t r[4], bh0[2], bh1[2];
                ldsm4(r, stK + off);
                bh0[0] = r[0]; bh0[1] = r[1]; bh1[0] = r[2]; bh1[1] = r[3];
                mma16816(sacc[2 * nh],     qhf[ki], bh0);
                mma16816(sacc[2 * nh + 1], qhf[ki], bh1);
                mma16816(sacc[2 * nh],     qlf[ki], bh0);
                mma16816(sacc[2 * nh + 1], qlf[ki], bh1);
            }
        }

        // ---- online softmax ----
        float rmax0 = -1e30f, rmax1 = -1e30f;
        const int cq = 2 * (lane & 3);
#pragma unroll
        for (int ni = 0; ni < 8; ni++) {
            float mk0 = mks[s][ni * 8 + cq];
            float mk1 = mks[s][ni * 8 + cq + 1];
            sacc[ni][0] = sacc[ni][0] * ATT_SCALE + mk0;
            sacc[ni][1] = sacc[ni][1] * ATT_SCALE + mk1;
            sacc[ni][2] = sacc[ni][2] * ATT_SCALE + mk0;
            sacc[ni][3] = sacc[ni][3] * ATT_SCALE + mk1;
            rmax0 = fmaxf(rmax0, fmaxf(sacc[ni][0], sacc[ni][1]));
            rmax1 = fmaxf(rmax1, fmaxf(sacc[ni][2], sacc[ni][3]));
        }
        rmax0 = fmaxf(rmax0, __shfl_xor_sync(0xffffffffu, rmax0, 1));
        rmax0 = fmaxf(rmax0, __shfl_xor_sync(0xffffffffu, rmax0, 2));
        rmax1 = fmaxf(rmax1, __shfl_xor_sync(0xffffffffu, rmax1, 1));
        rmax1 = fmaxf(rmax1, __shfl_xor_sync(0xffffffffu, rmax1, 2));

        float mn0 = fmaxf(m0, rmax0), mn1 = fmaxf(m1, rmax1);
        float a0 = __expf(m0 - mn0), a1 = __expf(m1 - mn1);
        m0 = mn0; m1 = mn1;

        float rs0 = 0.f, rs1 = 0.f;
#pragma unroll
        for (int ni = 0; ni < 8; ni++) {
            sacc[ni][0] = __expf(sacc[ni][0] - mn0);
            sacc[ni][1] = __expf(sacc[ni][1] - mn0);
            sacc[ni][2] = __expf(sacc[ni][2] - mn1);
            sacc[ni][3] = __expf(sacc[ni][3] - mn1);
            rs0 += sacc[ni][0] + sacc[ni][1];
            rs1 += sacc[ni][2] + sacc[ni][3];
        }
        rs0 += __shfl_xor_sync(0xffffffffu, rs0, 1);
        rs0 += __shfl_xor_sync(0xffffffffu, rs0, 2);
        rs1 += __shfl_xor_sync(0xffffffffu, rs1, 1);
        rs1 += __shfl_xor_sync(0xffffffffu, rs1, 2);
        l0 = l0 * a0 + rs0;
        l1 = l1 * a1 + rs1;
#pragma unroll
        for (int ni = 0; ni < 8; ni++) {
            oacc[ni][0] *= a0; oacc[ni][1] *= a0;
            oacc[ni][2] *= a1; oacc[ni][3] *= a1;
        }

        // ---- O += P V (2-term: ph*vh + pl*vh) ----
#pragma unroll
        for (int ki = 0; ki < 4; ki++) {
            uint32_t ph[4], pl[4];
            float* p0 = sacc[2 * ki];
            float* p1 = sacc[2 * ki + 1];
            ph[0] = packh(p0[0], p0[1]);
            ph[1] = packh(p0[2], p0[3]);
            ph[2] = packh(p1[0], p1[1]);
            ph[3] = packh(p1[2], p1[3]);
#pragma unroll
            for (int e = 0; e < 4; e++) {
                float* pp = (e < 2) ? p0 : p1;
                int b0 = (e & 1) * 2;
                float lo0 = pp[b0]     - __half2float(__float2half_rn(pp[b0]));
                float lo1 = pp[b0 + 1] - __half2float(__float2half_rn(pp[b0 + 1]));
                pl[e] = packh(lo0, lo1);
            }
#pragma unroll
            for (int nh = 0; nh < 4; nh++) {
                uint32_t off = (uint32_t)(ki * 16 + vrow) * FROWB + nh * 32 + vg;
                uint32_t r[4], vh0[2], vh1[2];
                ldsm4t(r, stV + off);
                vh0[0] = r[0]; vh0[1] = r[1]; vh1[0] = r[2]; vh1[1] = r[3];
                mma16816(oacc[2 * nh],     ph, vh0);
                mma16816(oacc[2 * nh + 1], ph, vh1);
                mma16816(oacc[2 * nh],     pl, vh0);
                mma16816(oacc[2 * nh + 1], pl, vh1);
            }
        }
    }

    // ---- epilogue: normalize, split fp16 hi/lo, write [token][h*64+d] ----
    float inv0 = 1.0f / l0, inv1 = 1.0f / l1;
    const int tok0 = b * Ll + qt * 128 + wid * 16 + (lane >> 2);
    const int cbase = h * 64 + 2 * (lane & 3);
#pragma unroll
    for (int ni = 0; ni < 8; ni++) {
        float v00 = oacc[ni][0] * inv0, v01 = oacc[ni][1] * inv0;
        float v10 = oacc[ni][2] * inv1, v11 = oacc[ni][3] * inv1;
        size_t o0 = (size_t)tok0 * Dd + cbase + ni * 8;
        size_t o1 = (size_t)(tok0 + 8) * Dd + cbase + ni * 8;
        uint32_t h00 = packh(v00, v01), h10 = packh(v10, v11);
        *(uint32_t*)&g_aohi[o0] = h00;
        *(uint32_t*)&g_aohi[o1] = h10;
        __half2 hh0 = *(__half2*)&h00;
        __half2 hh1 = *(__half2*)&h10;
        *(uint32_t*)&g_aolo[o0] = packh(v00 - __half2float(hh0.x),
                                        v01 - __half2float(hh0.y));
        *(uint32_t*)&g_aolo[o1] = packh(v10 - __half2float(hh1.x),
                                        v11 - __half2float(hh1.y));
    }
}

// ---------------------------------------------------------------------------
extern "C" void kernel_launch(void* const* d_in, const int* in_sizes, int n_in,
                              void* d_out, int out_size)
{
    const float* x    = (const float*)d_in[0];
    const float* rc   = (const float*)d_in[1];
    const float* rs   = (const float*)d_in[2];
    const float* wqkv = (const float*)d_in[3];
    const float* wo   = (const float*)d_in[4];
    const int*   mask = (const int*)d_in[5];
    float* out = (float*)d_out;

    float *qkv_p;
    __half *xhi, *xlo, *aohi, *aolo, *wqTh, *woTh;
    cudaGetSymbolAddress((void**)&qkv_p, g_qkv);
    cudaGetSymbolAddress((void**)&xhi, g_xhi);
    cudaGetSymbolAddress((void**)&xlo, g_xlo);
    cudaGetSymbolAddress((void**)&aohi, g_aohi);
    cudaGetSymbolAddress((void**)&aolo, g_aolo);
    cudaGetSymbolAddress((void**)&wqTh, g_wqTh);
    cudaGetSymbolAddress((void**)&woTh, g_woTh);

    const int GSM = 2 * (int)STAGE3;    // 61440
    cudaFuncSetAttribute((const void*)gemm_mma,
                         cudaFuncAttributeMaxDynamicSharedMemorySize, GSM);
    cudaFuncSetAttribute((const void*)flash_mma,
                         cudaFuncAttributeMaxDynamicSharedMemorySize, (int)FSMEM);

    // 0) splits
    split_hilo<<<(NT * Dd / 4) / 256, 256>>>(x, xhi, xlo);
    splitT<<<dim3(3 * Dd / 32, Dd / 32), dim3(32, 8)>>>(wqkv, wqTh, Dd, 3 * Dd);
    splitT<<<dim3(Dd / 32, Dd / 32), dim3(32, 8)>>>(wo, woTh, Dd, Dd);

    // 1) QKV projection (fp16 2-term HMMA)
    gemm_mma<<<dim3(3 * Dd / 128, NT / 128), 256, GSM>>>(xhi, xlo, wqTh,
                                                         qkv_p, NT, 3 * Dd, Dd);

    // 2) RoPE -> head-major fp16
    rope_kernel<<<(NT * Hh * 32) / 256, 256>>>(rc, rs);

    // 3) Flash attention (fp16 2-term HMMA)
    flash_mma<<<dim3(Ll / 128, Hh, Bb), 256, FSMEM>>>(mask);

    // 4) Output projection (fp16 2-term HMMA)
    gemm_mma<<<dim3(Dd / 128, NT / 128), 256, GSM>>>(aohi, aolo, woTh,
                                                     out, NT, Dd, Dd);
}

// round 8
// speedup vs baseline: 2.2428x; 1.6172x over previous
#include <cuda_runtime.h>
#include <cuda_fp16.h>
#include <math.h>
#include <stdint.h>

#define Bb 2
#define Ll 2048
#define Dd 1024
#define Hh 16
#define NT (Bb*Ll)          // 4096 tokens
#define ATT_SCALE 0.125f    // 1/sqrt(64)

// ---------------------------------------------------------------------------
// Scratch (device globals — allocation-free per harness rules)
// ---------------------------------------------------------------------------
__device__ float g_qkv[(size_t)NT * 3 * Dd];   // [token][3*D]

__device__ __half g_xh[(size_t)NT * Dd];
__device__ __half g_aoh[(size_t)NT * Dd];      // attn out [token][h*64+d]
__device__ __half g_wqTh[(size_t)3 * Dd * Dd]; // W_qkv^T [3072][1024]
__device__ __half g_woTh[(size_t)Dd * Dd];     // W_o^T
// head-major [b][h][l][64] fp16
__device__ __half g_qh[(size_t)NT * Dd];
__device__ __half g_kh[(size_t)NT * Dd];
__device__ __half g_vh[(size_t)NT * Dd];

// ---------------------------------------------------------------------------
// helpers
// ---------------------------------------------------------------------------
__device__ __forceinline__ uint32_t smem_u32(const void* p) {
    uint32_t a;
    asm("{ .reg .u64 t; cvta.to.shared.u64 t, %1; cvt.u32.u64 %0, t; }"
        : "=r"(a) : "l"(p));
    return a;
}
__device__ __forceinline__ void ldsm4(uint32_t* r, uint32_t addr) {
    asm volatile("ldmatrix.sync.aligned.m8n8.x4.shared.b16 {%0,%1,%2,%3}, [%4];"
        : "=r"(r[0]), "=r"(r[1]), "=r"(r[2]), "=r"(r[3]) : "r"(addr));
}
__device__ __forceinline__ void ldsm4t(uint32_t* r, uint32_t addr) {
    asm volatile("ldmatrix.sync.aligned.m8n8.x4.trans.shared.b16 {%0,%1,%2,%3}, [%4];"
        : "=r"(r[0]), "=r"(r[1]), "=r"(r[2]), "=r"(r[3]) : "r"(addr));
}
__device__ __forceinline__ void mma16816(float* d, const uint32_t* a, const uint32_t* b) {
    asm volatile("mma.sync.aligned.m16n8k16.row.col.f32.f16.f16.f32 "
        "{%0,%1,%2,%3}, {%4,%5,%6,%7}, {%8,%9}, {%0,%1,%2,%3};"
        : "+f"(d[0]), "+f"(d[1]), "+f"(d[2]), "+f"(d[3])
        : "r"(a[0]), "r"(a[1]), "r"(a[2]), "r"(a[3]), "r"(b[0]), "r"(b[1]));
}
__device__ __forceinline__ void cp_async16(uint32_t sdst, const void* gsrc) {
    asm volatile("cp.async.cg.shared.global [%0], [%1], 16;" :: "r"(sdst), "l"(gsrc));
}
#define CP_COMMIT() asm volatile("cp.async.commit_group;" ::: "memory")
#define CP_WAIT0()  asm volatile("cp.async.wait_group 0;" ::: "memory")

__device__ __forceinline__ uint32_t packh(float a, float b) {
    __half2 h = __floats2half2_rn(a, b);
    return *(uint32_t*)&h;
}

// ---------------------------------------------------------------------------
// fp32 -> fp16 convert
// ---------------------------------------------------------------------------
__global__ void __launch_bounds__(256) to_half(const float* __restrict__ in,
                                               __half* __restrict__ hi)
{
    int i = blockIdx.x * 256 + threadIdx.x;
    float4 v = ((const float4*)in)[i];
    __half2* h2 = (__half2*)hi;
    h2[2 * i]     = __floats2half2_rn(v.x, v.y);
    h2[2 * i + 1] = __floats2half2_rn(v.z, v.w);
}

// ---------------------------------------------------------------------------
// transpose + fp16: W[K][N] fp32 -> hiT [N][K] fp16
// ---------------------------------------------------------------------------
__global__ void __launch_bounds__(256) splitT(const float* __restrict__ W,
                                              __half* __restrict__ hiT,
                                              int K, int N)
{
    __shared__ float t[32][33];
    int n0 = blockIdx.x * 32, k0 = blockIdx.y * 32;
    int tx = threadIdx.x, ty = threadIdx.y;
#pragma unroll
    for (int r = 0; r < 4; r++)
        t[ty + r * 8][tx] = W[(size_t)(k0 + ty + r * 8) * N + n0 + tx];
    __syncthreads();
#pragma unroll
    for (int r = 0; r < 4; r++) {
        int n = ty + r * 8;
        hiT[(size_t)(n0 + n) * K + k0 + tx] = __float2half_rn(t[tx][n]);
    }
}

// ---------------------------------------------------------------------------
// HMMA GEMM (fp16 single): C = Ah[M,K] @ Bh[N,K]^T
// 128x128 tile, 256 threads, K-chunk 32, 2 stages, 2 CTAs/SM.
// ---------------------------------------------------------------------------
#define ROWB 80u
#define TILEB (128u * ROWB)          // 10240
#define STG2 (2u * TILEB)            // 20480

__global__ void __launch_bounds__(256, 2) gemm_mma(const __half* __restrict__ Ah,
                                                   const __half* __restrict__ Bh,
                                                   float* __restrict__ C,
                                                   int M, int N, int K)
{
    extern __shared__ char gsm[];
    const uint32_t sb = smem_u32(gsm);

    const int tid = threadIdx.x;
    const int wid = tid >> 5, lane = tid & 31;
    const int tile_n = blockIdx.x * 128, tile_m = blockIdx.y * 128;
    const int wm = wid & 1, wn = wid >> 1;
    const int NC = K >> 5;

    auto prefetch = [&](int kc, int s) {
        const uint32_t st = sb + (uint32_t)s * STG2;
#pragma unroll
        for (int it = 0; it < 4; it++) {
            int idx = it * 256 + tid;        // 0..1023
            int mat = idx >> 9;              // 0..1
            int r = (idx >> 2) & 127;        // 0..127
            int q = idx & 3;                 // 16B quarter of 64B row
            const __half* src = mat ? Bh : Ah;
            int rbase = mat ? tile_n : tile_m;
            const void* gp = src + (size_t)(rbase + r) * K + kc * 32 + q * 8;
            cp_async16(st + (uint32_t)mat * TILEB + (uint32_t)r * ROWB + q * 16, gp);
        }
        CP_COMMIT();
    };

    float acc[4][4][4];
#pragma unroll
    for (int mi = 0; mi < 4; mi++)
#pragma unroll
        for (int ni = 0; ni < 4; ni++)
#pragma unroll
            for (int e = 0; e < 4; e++) acc[mi][ni][e] = 0.f;

    prefetch(0, 0);

    const uint32_t a_row = (uint32_t)(lane & 15);
    const uint32_t a_kgrp = (uint32_t)(lane >> 4) * 16;
    const uint32_t b_n = (uint32_t)((lane & 7) + ((lane >> 4) << 3));
    const uint32_t b_kgrp = (uint32_t)((lane >> 3) & 1) * 16;

    for (int kc = 0; kc < NC; kc++) {
        const int s = kc & 1;
        CP_WAIT0();
        __syncthreads();
        if (kc + 1 < NC) prefetch(kc + 1, s ^ 1);

        const uint32_t sA = sb + (uint32_t)s * STG2;
        const uint32_t sB = sA + TILEB;

#pragma unroll
        for (int k16 = 0; k16 < 2; k16++) {
            const uint32_t kb = (uint32_t)k16 * 32;
            uint32_t ah[4][4], bh[4][2];
#pragma unroll
            for (int mi = 0; mi < 4; mi++) {
                uint32_t off = (uint32_t)(wm * 64 + mi * 16 + a_row) * ROWB + kb + a_kgrp;
                ldsm4(ah[mi], sA + off);
            }
#pragma unroll
            for (int nh = 0; nh < 2; nh++) {
                uint32_t off = (uint32_t)(wn * 32 + nh * 16 + b_n) * ROWB + kb + b_kgrp;
                uint32_t r[4];
                ldsm4(r, sB + off);
                bh[nh * 2][0] = r[0]; bh[nh * 2][1] = r[1];
                bh[nh * 2 + 1][0] = r[2]; bh[nh * 2 + 1][1] = r[3];
            }
#pragma unroll
            for (int mi = 0; mi < 4; mi++)
#pragma unroll
                for (int ni = 0; ni < 4; ni++)
                    mma16816(acc[mi][ni], ah[mi], bh[ni]);
        }
    }

#pragma unroll
    for (int mi = 0; mi < 4; mi++) {
        const int r0 = tile_m + wm * 64 + mi * 16 + (lane >> 2);
#pragma unroll
        for (int ni = 0; ni < 4; ni++) {
            const int c = tile_n + wn * 32 + ni * 8 + 2 * (lane & 3);
            *(float2*)&C[(size_t)r0 * N + c] =
                make_float2(acc[mi][ni][0], acc[mi][ni][1]);
            *(float2*)&C[(size_t)(r0 + 8) * N + c] =
                make_float2(acc[mi][ni][2], acc[mi][ni][3]);
        }
    }
}

// ---------------------------------------------------------------------------
// RoPE: g_qkv fp32 -> head-major fp16 q,k,v
// ---------------------------------------------------------------------------
__global__ void __launch_bounds__(256) rope_kernel(const float* __restrict__ cosb,
                                                   const float* __restrict__ sinb)
{
    int idx = blockIdx.x * blockDim.x + threadIdx.x;   // < NT*Hh*32
    int i = idx & 31;
    int h = (idx >> 5) & 15;
    int t = idx >> 9;
    int b = t >> 11;
    int l = t & (Ll - 1);

    float c = cosb[(size_t)t * (Dd / 2) + h * 32 + i];
    float s = sinb[(size_t)t * (Dd / 2) + h * 32 + i];

    const float* row = &g_qkv[(size_t)t * 3 * Dd];
    float q1 = row[h * 64 + i],            q2 = row[h * 64 + 32 + i];
    float k1 = row[Dd + h * 64 + i],       k2 = row[Dd + h * 64 + 32 + i];
    float v1 = row[2 * Dd + h * 64 + i],   v2 = row[2 * Dd + h * 64 + 32 + i];

    size_t o = ((size_t)(b * Hh + h) * Ll + l) * 64;
    g_qh[o + i]      = __float2half_rn(q1 * c - q2 * s);
    g_qh[o + 32 + i] = __float2half_rn(q1 * s + q2 * c);
    g_kh[o + i]      = __float2half_rn(k1 * c - k2 * s);
    g_kh[o + 32 + i] = __float2half_rn(k1 * s + k2 * c);
    g_vh[o + i]      = __float2half_rn(v1);
    g_vh[o + 32 + i] = __float2half_rn(v2);
}

// ---------------------------------------------------------------------------
// HMMA flash attention (fp16 single-precision operands).
// CTA: 128 q-rows of one (b,h). 8 warps. KV tile 64, double buffered.
// smem: stage s in {0,1}: Kh[64x144] Vh[64x144]; Q[128x144] once.
// ---------------------------------------------------------------------------
#define FROWB 144u
#define FMATB (64u * FROWB)     // 9216
#define FSTG (2u * FMATB)       // 18432 per stage
#define FQOFF (2u * FSTG)       // 36864
#define FSMEM (FQOFF + 128u * FROWB)   // 55296

__global__ void __launch_bounds__(256, 2) flash_mma(const int* __restrict__ mask)
{
    extern __shared__ char fsm_[];
    const uint32_t sb = smem_u32(fsm_);
    __shared__ float mks[2][64];

    const int qt = blockIdx.x, h = blockIdx.y, b = blockIdx.z;
    const int tid = threadIdx.x;
    const int wid = tid >> 5, lane = tid & 31;

    const size_t hoff = (size_t)(b * Hh + h) * Ll * 64;
    const __half* Kh = g_kh + hoff;
    const __half* Vh = g_vh + hoff;

    // ---- prologue: stage Q, prefetch KV tile 0 ----
    {
        const __half* Qs = g_qh + hoff;
#pragma unroll
        for (int it = 0; it < 4; it++) {
            int idx = it * 256 + tid;           // 0..1023
            int r = (idx >> 3) & 127;           // 0..127
            int q = idx & 7;                    // 0..7 (16B chunks, 128B row)
            const void* gp = Qs + (size_t)(qt * 128 + r) * 64 + q * 8;
            uint32_t sp = sb + FQOFF + r * FROWB + q * 16;
            cp_async16(sp, gp);
        }
        CP_COMMIT();
    }
    // KV: 2 mats x 64 rows x 8 quarters = 1024 chunks -> 4 iters
    auto prefetch = [&](int t, int s) {
#pragma unroll
        for (int it = 0; it < 4; it++) {
            int idx = it * 256 + tid;           // 0..1023
            int mat = idx >> 9;                 // 0..1 (K,V)
            int r = (idx >> 3) & 63;            // 0..63
            int q = idx & 7;                    // 0..7
            const __half* src = mat ? Vh : Kh;
            const void* gp = src + (size_t)(t * 64 + r) * 64 + q * 8;
            uint32_t sp = sb + (uint32_t)s * FSTG + mat * FMATB + r * FROWB + q * 16;
            cp_async16(sp, gp);
        }
        CP_COMMIT();
        if (tid < 64)
            mks[s][tid] = mask[b * Ll + t * 64 + tid] ? 0.0f : -1e30f;
    };
    prefetch(0, 0);
    CP_WAIT0();
    __syncthreads();

    // ---- extract Q fragments (register-resident) ----
    uint32_t qhf[4][4];
    {
        const uint32_t qrow = (uint32_t)(lane & 15);
        const uint32_t qg = (uint32_t)(lane >> 4) * 16;
#pragma unroll
        for (int ki = 0; ki < 4; ki++) {
            uint32_t off = (uint32_t)(wid * 16 + qrow) * FROWB + ki * 32 + qg;
            ldsm4(qhf[ki], sb + FQOFF + off);
        }
    }

    float oacc[8][4];
#pragma unroll
    for (int ni = 0; ni < 8; ni++)
#pragma unroll
        for (int e = 0; e < 4; e++) oacc[ni][e] = 0.f;
    float m0 = -1e30f, m1 = -1e30f, l0 = 0.f, l1 = 0.f;

    const uint32_t krow = (uint32_t)((lane & 7) + ((lane >> 4) << 3));
    const uint32_t kg = (uint32_t)((lane >> 3) & 1) * 16;
    const uint32_t vrow = (uint32_t)(lane & 15);
    const uint32_t vg = (uint32_t)(lane >> 4) * 16;

    for (int t = 0; t < Ll / 64; t++) {
        const int s = t & 1;
        CP_WAIT0();
        __syncthreads();
        if (t + 1 < Ll / 64) prefetch(t + 1, s ^ 1);

        const uint32_t stK = sb + (uint32_t)s * FSTG;
        const uint32_t stV = stK + FMATB;

        // ---- S = Q K^T ----
        float sacc[8][4];
#pragma unroll
        for (int ni = 0; ni < 8; ni++)
#pragma unroll
            for (int e = 0; e < 4; e++) sacc[ni][e] = 0.f;

#pragma unroll
        for (int nh = 0; nh < 4; nh++) {
#pragma unroll
            for (int ki = 0; ki < 4; ki++) {
                uint32_t off = (uint32_t)(nh * 16 + krow) * FROWB + ki * 32 + kg;
                uint32_t r[4], bh0[2], bh1[2];
                ldsm4(r, stK + off);
                bh0[0] = r[0]; bh0[1] = r[1]; bh1[0] = r[2]; bh1[1] = r[3];
                mma16816(sacc[2 * nh],     qhf[ki], bh0);
                mma16816(sacc[2 * nh + 1], qhf[ki], bh1);
            }
        }

        // ---- online softmax ----
        float rmax0 = -1e30f, rmax1 = -1e30f;
        const int cq = 2 * (lane & 3);
#pragma unroll
        for (int ni = 0; ni < 8; ni++) {
            float mk0 = mks[s][ni * 8 + cq];
            float mk1 = mks[s][ni * 8 + cq + 1];
            sacc[ni][0] = sacc[ni][0] * ATT_SCALE + mk0;
            sacc[ni][1] = sacc[ni][1] * ATT_SCALE + mk1;
            sacc[ni][2] = sacc[ni][2] * ATT_SCALE + mk0;
            sacc[ni][3] = sacc[ni][3] * ATT_SCALE + mk1;
            rmax0 = fmaxf(rmax0, fmaxf(sacc[ni][0], sacc[ni][1]));
            rmax1 = fmaxf(rmax1, fmaxf(sacc[ni][2], sacc[ni][3]));
        }
        rmax0 = fmaxf(rmax0, __shfl_xor_sync(0xffffffffu, rmax0, 1));
        rmax0 = fmaxf(rmax0, __shfl_xor_sync(0xffffffffu, rmax0, 2));
        rmax1 = fmaxf(rmax1, __shfl_xor_sync(0xffffffffu, rmax1, 1));
        rmax1 = fmaxf(rmax1, __shfl_xor_sync(0xffffffffu, rmax1, 2));

        float mn0 = fmaxf(m0, rmax0), mn1 = fmaxf(m1, rmax1);
        float a0 = __expf(m0 - mn0), a1 = __expf(m1 - mn1);
        m0 = mn0; m1 = mn1;

        float rs0 = 0.f, rs1 = 0.f;
#pragma unroll
        for (int ni = 0; ni < 8; ni++) {
            sacc[ni][0] = __expf(sacc[ni][0] - mn0);
            sacc[ni][1] = __expf(sacc[ni][1] - mn0);
            sacc[ni][2] = __expf(sacc[ni][2] - mn1);
            sacc[ni][3] = __expf(sacc[ni][3] - mn1);
            rs0 += sacc[ni][0] + sacc[ni][1];
            rs1 += sacc[ni][2] + sacc[ni][3];
        }
        rs0 += __shfl_xor_sync(0xffffffffu, rs0, 1);
        rs0 += __shfl_xor_sync(0xffffffffu, rs0, 2);
        rs1 += __shfl_xor_sync(0xffffffffu, rs1, 1);
        rs1 += __shfl_xor_sync(0xffffffffu, rs1, 2);
        l0 = l0 * a0 + rs0;
        l1 = l1 * a1 + rs1;
#pragma unroll
        for (int ni = 0; ni < 8; ni++) {
            oacc[ni][0] *= a0; oacc[ni][1] *= a0;
            oacc[ni][2] *= a1; oacc[ni][3] *= a1;
        }

        // ---- O += P V ----
#pragma unroll
        for (int ki = 0; ki < 4; ki++) {
            uint32_t ph[4];
            float* p0 = sacc[2 * ki];
            float* p1 = sacc[2 * ki + 1];
            ph[0] = packh(p0[0], p0[1]);
            ph[1] = packh(p0[2], p0[3]);
            ph[2] = packh(p1[0], p1[1]);
            ph[3] = packh(p1[2], p1[3]);
#pragma unroll
            for (int nh = 0; nh < 4; nh++) {
                uint32_t off = (uint32_t)(ki * 16 + vrow) * FROWB + nh * 32 + vg;
                uint32_t r[4], vh0[2], vh1[2];
                ldsm4t(r, stV + off);
                vh0[0] = r[0]; vh0[1] = r[1]; vh1[0] = r[2]; vh1[1] = r[3];
                mma16816(oacc[2 * nh],     ph, vh0);
                mma16816(oacc[2 * nh + 1], ph, vh1);
            }
        }
    }

    // ---- epilogue: normalize, write fp16 [token][h*64+d] ----
    float inv0 = 1.0f / l0, inv1 = 1.0f / l1;
    const int tok0 = b * Ll + qt * 128 + wid * 16 + (lane >> 2);
    const int cbase = h * 64 + 2 * (lane & 3);
#pragma unroll
    for (int ni = 0; ni < 8; ni++) {
        size_t o0 = (size_t)tok0 * Dd + cbase + ni * 8;
        size_t o1 = (size_t)(tok0 + 8) * Dd + cbase + ni * 8;
        *(uint32_t*)&g_aoh[o0] = packh(oacc[ni][0] * inv0, oacc[ni][1] * inv0);
        *(uint32_t*)&g_aoh[o1] = packh(oacc[ni][2] * inv1, oacc[ni][3] * inv1);
    }
}

// ---------------------------------------------------------------------------
extern "C" void kernel_launch(void* const* d_in, const int* in_sizes, int n_in,
                              void* d_out, int out_size)
{
    const float* x    = (const float*)d_in[0];
    const float* rc   = (const float*)d_in[1];
    const float* rs   = (const float*)d_in[2];
    const float* wqkv = (const float*)d_in[3];
    const float* wo   = (const float*)d_in[4];
    const int*   mask = (const int*)d_in[5];
    float* out = (float*)d_out;

    float *qkv_p;
    __half *xh, *aoh, *wqTh, *woTh;
    cudaGetSymbolAddress((void**)&qkv_p, g_qkv);
    cudaGetSymbolAddress((void**)&xh, g_xh);
    cudaGetSymbolAddress((void**)&aoh, g_aoh);
    cudaGetSymbolAddress((void**)&wqTh, g_wqTh);
    cudaGetSymbolAddress((void**)&woTh, g_woTh);

    const int GSM = 2 * (int)STG2;      // 40960
    cudaFuncSetAttribute((const void*)gemm_mma,
                         cudaFuncAttributeMaxDynamicSharedMemorySize, GSM);
    cudaFuncSetAttribute((const void*)flash_mma,
                         cudaFuncAttributeMaxDynamicSharedMemorySize, (int)FSMEM);

    // 0) convert inputs
    to_half<<<(NT * Dd / 4) / 256, 256>>>(x, xh);
    splitT<<<dim3(3 * Dd / 32, Dd / 32), dim3(32, 8)>>>(wqkv, wqTh, Dd, 3 * Dd);
    splitT<<<dim3(Dd / 32, Dd / 32), dim3(32, 8)>>>(wo, woTh, Dd, Dd);

    // 1) QKV projection (fp16 HMMA)
    gemm_mma<<<dim3(3 * Dd / 128, NT / 128), 256, GSM>>>(xh, wqTh,
                                                         qkv_p, NT, 3 * Dd, Dd);

    // 2) RoPE -> head-major fp16
    rope_kernel<<<(NT * Hh * 32) / 256, 256>>>(rc, rs);

    // 3) Flash attention (fp16 HMMA)
    flash_mma<<<dim3(Ll / 128, Hh, Bb), 256, FSMEM>>>(mask);

    // 4) Output projection (fp16 HMMA)
    gemm_mma<<<dim3(Dd / 128, NT / 128), 256, GSM>>>(aoh, woTh,
                                                     out, NT, Dd, Dd);
}

// round 9
// speedup vs baseline: 2.4804x; 1.1059x over previous
#include <cuda_runtime.h>
#include <cuda_fp16.h>
#include <math.h>
#include <stdint.h>

#define Bb 2
#define Ll 2048
#define Dd 1024
#define Hh 16
#define NT (Bb*Ll)          // 4096 tokens
#define SCALE_L2E 0.18033688011112428f   // (1/sqrt(64)) * log2(e)

// ---------------------------------------------------------------------------
// Scratch (device globals — allocation-free per harness rules)
// ---------------------------------------------------------------------------
__device__ float g_qkv[(size_t)NT * 3 * Dd];   // [token][3*D]

__device__ __half g_xh[(size_t)NT * Dd];
__device__ __half g_aoh[(size_t)NT * Dd];      // attn out [token][h*64+d]
__device__ __half g_wqTh[(size_t)3 * Dd * Dd]; // W_qkv^T [3072][1024]
__device__ __half g_woTh[(size_t)Dd * Dd];     // W_o^T
// head-major [b][h][l][64] fp16
__device__ __half g_qh[(size_t)NT * Dd];
__device__ __half g_kh[(size_t)NT * Dd];
__device__ __half g_vh[(size_t)NT * Dd];

// ---------------------------------------------------------------------------
// helpers
// ---------------------------------------------------------------------------
__device__ __forceinline__ uint32_t smem_u32(const void* p) {
    uint32_t a;
    asm("{ .reg .u64 t; cvta.to.shared.u64 t, %1; cvt.u32.u64 %0, t; }"
        : "=r"(a) : "l"(p));
    return a;
}
__device__ __forceinline__ void ldsm4(uint32_t* r, uint32_t addr) {
    asm volatile("ldmatrix.sync.aligned.m8n8.x4.shared.b16 {%0,%1,%2,%3}, [%4];"
        : "=r"(r[0]), "=r"(r[1]), "=r"(r[2]), "=r"(r[3]) : "r"(addr));
}
__device__ __forceinline__ void ldsm4t(uint32_t* r, uint32_t addr) {
    asm volatile("ldmatrix.sync.aligned.m8n8.x4.trans.shared.b16 {%0,%1,%2,%3}, [%4];"
        : "=r"(r[0]), "=r"(r[1]), "=r"(r[2]), "=r"(r[3]) : "r"(addr));
}
__device__ __forceinline__ void mma16816(float* d, const uint32_t* a, const uint32_t* b) {
    asm volatile("mma.sync.aligned.m16n8k16.row.col.f32.f16.f16.f32 "
        "{%0,%1,%2,%3}, {%4,%5,%6,%7}, {%8,%9}, {%0,%1,%2,%3};"
        : "+f"(d[0]), "+f"(d[1]), "+f"(d[2]), "+f"(d[3])
        : "r"(a[0]), "r"(a[1]), "r"(a[2]), "r"(a[3]), "r"(b[0]), "r"(b[1]));
}
__device__ __forceinline__ void cp_async16(uint32_t sdst, const void* gsrc) {
    asm volatile("cp.async.cg.shared.global [%0], [%1], 16;" :: "r"(sdst), "l"(gsrc));
}
#define CP_COMMIT() asm volatile("cp.async.commit_group;" ::: "memory")
#define CP_WAIT0()  asm volatile("cp.async.wait_group 0;" ::: "memory")

__device__ __forceinline__ uint32_t packh(float a, float b) {
    __half2 h = __floats2half2_rn(a, b);
    return *(uint32_t*)&h;
}
__device__ __forceinline__ float ex2f(float x) {
    float y;
    asm("ex2.approx.f32 %0, %1;" : "=f"(y) : "f"(x));
    return y;
}

// ---------------------------------------------------------------------------
// fp32 -> fp16 convert
// ---------------------------------------------------------------------------
__global__ void __launch_bounds__(256) to_half(const float* __restrict__ in,
                                               __half* __restrict__ hi)
{
    int i = blockIdx.x * 256 + threadIdx.x;
    float4 v = ((const float4*)in)[i];
    __half2* h2 = (__half2*)hi;
    h2[2 * i]     = __floats2half2_rn(v.x, v.y);
    h2[2 * i + 1] = __floats2half2_rn(v.z, v.w);
}

// ---------------------------------------------------------------------------
// transpose + fp16: W[K][N] fp32 -> hiT [N][K] fp16
// ---------------------------------------------------------------------------
__global__ void __launch_bounds__(256) splitT(const float* __restrict__ W,
                                              __half* __restrict__ hiT,
                                              int K, int N)
{
    __shared__ float t[32][33];
    int n0 = blockIdx.x * 32, k0 = blockIdx.y * 32;
    int tx = threadIdx.x, ty = threadIdx.y;
#pragma unroll
    for (int r = 0; r < 4; r++)
        t[ty + r * 8][tx] = W[(size_t)(k0 + ty + r * 8) * N + n0 + tx];
    __syncthreads();
#pragma unroll
    for (int r = 0; r < 4; r++) {
        int n = ty + r * 8;
        hiT[(size_t)(n0 + n) * K + k0 + tx] = __float2half_rn(t[tx][n]);
    }
}

// ---------------------------------------------------------------------------
// HMMA GEMM (fp16): C = Ah[M,K] @ Bh[N,K]^T
// CTA tile 128x128, 128 threads (4 warps), warp tile 64x64 (wm 0..1, wn 0..1).
// K-chunk 32, 2 stages, 2 CTAs/SM.
// ---------------------------------------------------------------------------
#define ROWB 80u
#define TILEB (128u * ROWB)          // 10240
#define STG2 (2u * TILEB)            // 20480 per stage

__global__ void __launch_bounds__(128, 2) gemm_mma(const __half* __restrict__ Ah,
                                                   const __half* __restrict__ Bh,
                                                   float* __restrict__ C,
                                                   int M, int N, int K)
{
    extern __shared__ char gsm[];
    const uint32_t sb = smem_u32(gsm);

    const int tid = threadIdx.x;
    const int wid = tid >> 5, lane = tid & 31;
    const int tile_n = blockIdx.x * 128, tile_m = blockIdx.y * 128;
    const int wm = wid & 1, wn = wid >> 1;
    const int NC = K >> 5;

    // 256 rows (128 A + 128 B) x 4 sixteen-byte quarters = 1024 ops, 8/thread
    auto prefetch = [&](int kc, int s) {
        const uint32_t st = sb + (uint32_t)s * STG2;
#pragma unroll
        for (int it = 0; it < 8; it++) {
            int idx = it * 128 + tid;        // 0..1023
            int r = idx >> 2;                // 0..255
            int q = idx & 3;
            int mat = r >> 7;                // 0=A, 1=B
            int row = r & 127;
            const __half* src = mat ? Bh : Ah;
            int rbase = mat ? tile_n : tile_m;
            const void* gp = src + (size_t)(rbase + row) * K + kc * 32 + q * 8;
            cp_async16(st + (uint32_t)mat * TILEB + (uint32_t)row * ROWB + q * 16, gp);
        }
        CP_COMMIT();
    };

    float acc[4][8][4];
#pragma unroll
    for (int mi = 0; mi < 4; mi++)
#pragma unroll
        for (int ni = 0; ni < 8; ni++)
#pragma unroll
            for (int e = 0; e < 4; e++) acc[mi][ni][e] = 0.f;

    prefetch(0, 0);

    const uint32_t a_row = (uint32_t)(lane & 15);
    const uint32_t a_kgrp = (uint32_t)(lane >> 4) * 16;
    const uint32_t b_n = (uint32_t)((lane & 7) + ((lane >> 4) << 3));
    const uint32_t b_kgrp = (uint32_t)((lane >> 3) & 1) * 16;

    for (int kc = 0; kc < NC; kc++) {
        const int s = kc & 1;
        CP_WAIT0();
        __syncthreads();
        if (kc + 1 < NC) prefetch(kc + 1, s ^ 1);

        const uint32_t sA = sb + (uint32_t)s * STG2;
        const uint32_t sB = sA + TILEB;

#pragma unroll
        for (int k16 = 0; k16 < 2; k16++) {
            const uint32_t kb = (uint32_t)k16 * 32;
            uint32_t ah[4][4], bh[8][2];
#pragma unroll
            for (int mi = 0; mi < 4; mi++) {
                uint32_t off = (uint32_t)(wm * 64 + mi * 16 + a_row) * ROWB + kb + a_kgrp;
                ldsm4(ah[mi], sA + off);
            }
#pragma unroll
            for (int nh = 0; nh < 4; nh++) {
                uint32_t off = (uint32_t)(wn * 64 + nh * 16 + b_n) * ROWB + kb + b_kgrp;
                uint32_t r[4];
                ldsm4(r, sB + off);
                bh[nh * 2][0] = r[0]; bh[nh * 2][1] = r[1];
                bh[nh * 2 + 1][0] = r[2]; bh[nh * 2 + 1][1] = r[3];
            }
#pragma unroll
            for (int mi = 0; mi < 4; mi++)
#pragma unroll
                for (int ni = 0; ni < 8; ni++)
                    mma16816(acc[mi][ni], ah[mi], bh[ni]);
        }
    }

#pragma unroll
    for (int mi = 0; mi < 4; mi++) {
        const int r0 = tile_m + wm * 64 + mi * 16 + (lane >> 2);
#pragma unroll
        for (int ni = 0; ni < 8; ni++) {
            const int c = tile_n + wn * 64 + ni * 8 + 2 * (lane & 3);
            *(float2*)&C[(size_t)r0 * N + c] =
                make_float2(acc[mi][ni][0], acc[mi][ni][1]);
            *(float2*)&C[(size_t)(r0 + 8) * N + c] =
                make_float2(acc[mi][ni][2], acc[mi][ni][3]);
        }
    }
}

// ---------------------------------------------------------------------------
// RoPE: g_qkv fp32 -> head-major fp16 q,k,v
// ---------------------------------------------------------------------------
__global__ void __launch_bounds__(256) rope_kernel(const float* __restrict__ cosb,
                                                   const float* __restrict__ sinb)
{
    int idx = blockIdx.x * blockDim.x + threadIdx.x;   // < NT*Hh*32
    int i = idx & 31;
    int h = (idx >> 5) & 15;
    int t = idx >> 9;
    int b = t >> 11;
    int l = t & (Ll - 1);

    float c = cosb[(size_t)t * (Dd / 2) + h * 32 + i];
    float s = sinb[(size_t)t * (Dd / 2) + h * 32 + i];

    const float* row = &g_qkv[(size_t)t * 3 * Dd];
    float q1 = row[h * 64 + i],            q2 = row[h * 64 + 32 + i];
    float k1 = row[Dd + h * 64 + i],       k2 = row[Dd + h * 64 + 32 + i];
    float v1 = row[2 * Dd + h * 64 + i],   v2 = row[2 * Dd + h * 64 + 32 + i];

    size_t o = ((size_t)(b * Hh + h) * Ll + l) * 64;
    g_qh[o + i]      = __float2half_rn(q1 * c - q2 * s);
    g_qh[o + 32 + i] = __float2half_rn(q1 * s + q2 * c);
    g_kh[o + i]      = __float2half_rn(k1 * c - k2 * s);
    g_kh[o + 32 + i] = __float2half_rn(k1 * s + k2 * c);
    g_vh[o + i]      = __float2half_rn(v1);
    g_vh[o + 32 + i] = __float2half_rn(v2);
}

// ---------------------------------------------------------------------------
// HMMA flash attention (fp16 operands, log2-domain softmax).
// CTA: 128 q-rows of one (b,h). 8 warps. KV tile 64, double buffered.
// smem: stage s in {0,1}: Kh[64x144] Vh[64x144]; Q[128x144] once.
// ---------------------------------------------------------------------------
#define FROWB 144u
#define FMATB (64u * FROWB)     // 9216
#define FSTG (2u * FMATB)       // 18432 per stage
#define FQOFF (2u * FSTG)       // 36864
#define FSMEM (FQOFF + 128u * FROWB)   // 55296

__global__ void __launch_bounds__(256, 2) flash_mma(const int* __restrict__ mask)
{
    extern __shared__ char fsm_[];
    const uint32_t sb = smem_u32(fsm_);
    __shared__ float mks[2][64];

    const int qt = blockIdx.x, h = blockIdx.y, b = blockIdx.z;
    const int tid = threadIdx.x;
    const int wid = tid >> 5, lane = tid & 31;

    const size_t hoff = (size_t)(b * Hh + h) * Ll * 64;
    const __half* Kh = g_kh + hoff;
    const __half* Vh = g_vh + hoff;

    // ---- prologue: stage Q, prefetch KV tile 0 ----
    {
        const __half* Qs = g_qh + hoff;
#pragma unroll
        for (int it = 0; it < 4; it++) {
            int idx = it * 256 + tid;           // 0..1023
            int r = (idx >> 3) & 127;           // 0..127
            int q = idx & 7;                    // 0..7 (16B chunks, 128B row)
            const void* gp = Qs + (size_t)(qt * 128 + r) * 64 + q * 8;
            uint32_t sp = sb + FQOFF + r * FROWB + q * 16;
            cp_async16(sp, gp);
        }
        CP_COMMIT();
    }
    auto prefetch = [&](int t, int s) {
#pragma unroll
        for (int it = 0; it < 4; it++) {
            int idx = it * 256 + tid;           // 0..1023
            int mat = idx >> 9;                 // 0..1 (K,V)
            int r = (idx >> 3) & 63;            // 0..63
            int q = idx & 7;                    // 0..7
            const __half* src = mat ? Vh : Kh;
            const void* gp = src + (size_t)(t * 64 + r) * 64 + q * 8;
            uint32_t sp = sb + (uint32_t)s * FSTG + mat * FMATB + r * FROWB + q * 16;
            cp_async16(sp, gp);
        }
        CP_COMMIT();
        if (tid < 64)
            mks[s][tid] = mask[b * Ll + t * 64 + tid] ? 0.0f : -1e30f;
    };
    prefetch(0, 0);
    CP_WAIT0();
    __syncthreads();

    // ---- extract Q fragments (register-resident) ----
    uint32_t qhf[4][4];
    {
        const uint32_t qrow = (uint32_t)(lane & 15);
        const uint32_t qg = (uint32_t)(lane >> 4) * 16;
#pragma unroll
        for (int ki = 0; ki < 4; ki++) {
            uint32_t off = (uint32_t)(wid * 16 + qrow) * FROWB + ki * 32 + qg;
            ldsm4(qhf[ki], sb + FQOFF + off);
        }
    }

    float oacc[8][4];
#pragma unroll
    for (int ni = 0; ni < 8; ni++)
#pragma unroll
        for (int e = 0; e < 4; e++) oacc[ni][e] = 0.f;
    float m0 = -1e30f, m1 = -1e30f, l0 = 0.f, l1 = 0.f;

    const uint32_t krow = (uint32_t)((lane & 7) + ((lane >> 4) << 3));
    const uint32_t kg = (uint32_t)((lane >> 3) & 1) * 16;
    const uint32_t vrow = (uint32_t)(lane & 15);
    const uint32_t vg = (uint32_t)(lane >> 4) * 16;

    for (int t = 0; t < Ll / 64; t++) {
        const int s = t & 1;
        CP_WAIT0();
        __syncthreads();
        if (t + 1 < Ll / 64) prefetch(t + 1, s ^ 1);

        const uint32_t stK = sb + (uint32_t)s * FSTG;
        const uint32_t stV = stK + FMATB;

        // ---- S = Q K^T ----
        float sacc[8][4];
#pragma unroll
        for (int ni = 0; ni < 8; ni++)
#pragma unroll
            for (int e = 0; e < 4; e++) sacc[ni][e] = 0.f;

#pragma unroll
        for (int nh = 0; nh < 4; nh++) {
#pragma unroll
            for (int ki = 0; ki < 4; ki++) {
                uint32_t off = (uint32_t)(nh * 16 + krow) * FROWB + ki * 32 + kg;
                uint32_t r[4], bh0[2], bh1[2];
                ldsm4(r, stK + off);
                bh0[0] = r[0]; bh0[1] = r[1]; bh1[0] = r[2]; bh1[1] = r[3];
                mma16816(sacc[2 * nh],     qhf[ki], bh0);
                mma16816(sacc[2 * nh + 1], qhf[ki], bh1);
            }
        }

        // ---- online softmax (log2 domain) ----
        float rmax0 = -1e30f, rmax1 = -1e30f;
        const int cq = 2 * (lane & 3);
#pragma unroll
        for (int ni = 0; ni < 8; ni++) {
            float mk0 = mks[s][ni * 8 + cq];
            float mk1 = mks[s][ni * 8 + cq + 1];
            sacc[ni][0] = sacc[ni][0] * SCALE_L2E + mk0;
            sacc[ni][1] = sacc[ni][1] * SCALE_L2E + mk1;
            sacc[ni][2] = sacc[ni][2] * SCALE_L2E + mk0;
            sacc[ni][3] = sacc[ni][3] * SCALE_L2E + mk1;
            rmax0 = fmaxf(rmax0, fmaxf(sacc[ni][0], sacc[ni][1]));
            rmax1 = fmaxf(rmax1, fmaxf(sacc[ni][2], sacc[ni][3]));
        }
        rmax0 = fmaxf(rmax0, __shfl_xor_sync(0xffffffffu, rmax0, 1));
        rmax0 = fmaxf(rmax0, __shfl_xor_sync(0xffffffffu, rmax0, 2));
        rmax1 = fmaxf(rmax1, __shfl_xor_sync(0xffffffffu, rmax1, 1));
        rmax1 = fmaxf(rmax1, __shfl_xor_sync(0xffffffffu, rmax1, 2));

        float mn0 = fmaxf(m0, rmax0), mn1 = fmaxf(m1, rmax1);
        float a0 = ex2f(m0 - mn0), a1 = ex2f(m1 - mn1);
        m0 = mn0; m1 = mn1;

        float rs0 = 0.f, rs1 = 0.f;
#pragma unroll
        for (int ni = 0; ni < 8; ni++) {
            sacc[ni][0] = ex2f(sacc[ni][0] - mn0);
            sacc[ni][1] = ex2f(sacc[ni][1] - mn0);
            sacc[ni][2] = ex2f(sacc[ni][2] - mn1);
            sacc[ni][3] = ex2f(sacc[ni][3] - mn1);
            rs0 += sacc[ni][0] + sacc[ni][1];
            rs1 += sacc[ni][2] + sacc[ni][3];
        }
        rs0 += __shfl_xor_sync(0xffffffffu, rs0, 1);
        rs0 += __shfl_xor_sync(0xffffffffu, rs0, 2);
        rs1 += __shfl_xor_sync(0xffffffffu, rs1, 1);
        rs1 += __shfl_xor_sync(0xffffffffu, rs1, 2);
        l0 = l0 * a0 + rs0;
        l1 = l1 * a1 + rs1;
#pragma unroll
        for (int ni = 0; ni < 8; ni++) {
            oacc[ni][0] *= a0; oacc[ni][1] *= a0;
            oacc[ni][2] *= a1; oacc[ni][3] *= a1;
        }

        // ---- O += P V ----
#pragma unroll
        for (int ki = 0; ki < 4; ki++) {
            uint32_t ph[4];
            float* p0 = sacc[2 * ki];
            float* p1 = sacc[2 * ki + 1];
            ph[0] = packh(p0[0], p0[1]);
            ph[1] = packh(p0[2], p0[3]);
            ph[2] = packh(p1[0], p1[1]);
            ph[3] = packh(p1[2], p1[3]);
#pragma unroll
            for (int nh = 0; nh < 4; nh++) {
                uint32_t off = (uint32_t)(ki * 16 + vrow) * FROWB + nh * 32 + vg;
                uint32_t r[4], vh0[2], vh1[2];
                ldsm4t(r, stV + off);
                vh0[0] = r[0]; vh0[1] = r[1]; vh1[0] = r[2]; vh1[1] = r[3];
                mma16816(oacc[2 * nh],     ph, vh0);
                mma16816(oacc[2 * nh + 1], ph, vh1);
            }
        }
    }

    // ---- epilogue: normalize, write fp16 [token][h*64+d] ----
    float inv0 = 1.0f / l0, inv1 = 1.0f / l1;
    const int tok0 = b * Ll + qt * 128 + wid * 16 + (lane >> 2);
    const int cbase = h * 64 + 2 * (lane & 3);
#pragma unroll
    for (int ni = 0; ni < 8; ni++) {
        size_t o0 = (size_t)tok0 * Dd + cbase + ni * 8;
        size_t o1 = (size_t)(tok0 + 8) * Dd + cbase + ni * 8;
        *(uint32_t*)&g_aoh[o0] = packh(oacc[ni][0] * inv0, oacc[ni][1] * inv0);
        *(uint32_t*)&g_aoh[o1] = packh(oacc[ni][2] * inv1, oacc[ni][3] * inv1);
    }
}

// ---------------------------------------------------------------------------
extern "C" void kernel_launch(void* const* d_in, const int* in_sizes, int n_in,
                              void* d_out, int out_size)
{
    const float* x    = (const float*)d_in[0];
    const float* rc   = (const float*)d_in[1];
    const float* rs   = (const float*)d_in[2];
    const float* wqkv = (const float*)d_in[3];
    const float* wo   = (const float*)d_in[4];
    const int*   mask = (const int*)d_in[5];
    float* out = (float*)d_out;

    float *qkv_p;
    __half *xh, *aoh, *wqTh, *woTh;
    cudaGetSymbolAddress((void**)&qkv_p, g_qkv);
    cudaGetSymbolAddress((void**)&xh, g_xh);
    cudaGetSymbolAddress((void**)&aoh, g_aoh);
    cudaGetSymbolAddress((void**)&wqTh, g_wqTh);
    cudaGetSymbolAddress((void**)&woTh, g_woTh);

    const int GSM = 2 * (int)STG2;      // 40960
    cudaFuncSetAttribute((const void*)gemm_mma,
                         cudaFuncAttributeMaxDynamicSharedMemorySize, GSM);
    cudaFuncSetAttribute((const void*)flash_mma,
                         cudaFuncAttributeMaxDynamicSharedMemorySize, (int)FSMEM);

    // 0) convert inputs
    to_half<<<(NT * Dd / 4) / 256, 256>>>(x, xh);
    splitT<<<dim3(3 * Dd / 32, Dd / 32), dim3(32, 8)>>>(wqkv, wqTh, Dd, 3 * Dd);
    splitT<<<dim3(Dd / 32, Dd / 32), dim3(32, 8)>>>(wo, woTh, Dd, Dd);

    // 1) QKV projection (fp16 HMMA, 64x64 warp tiles)
    gemm_mma<<<dim3(3 * Dd / 128, NT / 128), 128, GSM>>>(xh, wqTh,
                                                         qkv_p, NT, 3 * Dd, Dd);

    // 2) RoPE -> head-major fp16
    rope_kernel<<<(NT * Hh * 32) / 256, 256>>>(rc, rs);

    // 3) Flash attention (fp16 HMMA)
    flash_mma<<<dim3(Ll / 128, Hh, Bb), 256, FSMEM>>>(mask);

    // 4) Output projection (fp16 HMMA)
    gemm_mma<<<dim3(Dd / 128, NT / 128), 128, GSM>>>(aoh, woTh,
                                                     out, NT, Dd, Dd);
}